// round 12
// baseline (speedup 1.0000x reference)
#include <cuda_runtime.h>
#include <cooperative_groups.h>

namespace cg = cooperative_groups;

// FPS, torch_geometric semantics. 16 clouds x 16384 -> 4096 samples/cloud.
// 4-CTA cluster per cloud (64 CTAs), 4096 points per CTA, min-dists in regs.
// Cross-CTA exchange: seqnum-stamped DSMEM slot records; owner does plain
// st.shared::cluster of the record then st.release.cluster of the iteration
// number; readers spin on LOCAL smem seq words with ld.acquire.cluster.
// No cluster.sync in the loop. skeys and slots parity-double-buffered; safety
// follows from the forward dependency (publish(i+2) requires barA(i+1) which
// requires all reads of iter i to be done).
// Warp reduce via redux.sync.max.u32 (key semantics identical to u64 shuffle).
// Bit-exact arithmetic (validated R6+): d=(dx*dx+dy*dy)+dz*dz, RN, no FMA
// contraction, sub = add of negated. argmax = first occurrence (lowest index).
// Output: float32 values of global indices.

#define N_CLOUDS 16
#define PTS      16384
#define M_SAMP   4096
#define THREADS  512
#define CL       4
#define QTR      4096    // points per CTA
#define PAIRS    4       // 8 points per thread = 4 f32x2 pairs

__device__ __forceinline__ unsigned long long pack2(float lo, float hi) {
    unsigned long long r;
    asm("mov.b64 %0, {%1, %2};" : "=l"(r) : "f"(lo), "f"(hi));
    return r;
}
__device__ __forceinline__ void unpack2(unsigned long long v, float& lo, float& hi) {
    asm("mov.b64 {%0, %1}, %2;" : "=f"(lo), "=f"(hi) : "l"(v));
}
__device__ __forceinline__ unsigned long long add2(unsigned long long a, unsigned long long b) {
    unsigned long long r;
    asm("add.rn.f32x2 %0, %1, %2;" : "=l"(r) : "l"(a), "l"(b));
    return r;
}
__device__ __forceinline__ unsigned long long mul2(unsigned long long a, unsigned long long b) {
    unsigned long long r;
    asm("mul.rn.f32x2 %0, %1, %2;" : "=l"(r) : "l"(a), "l"(b));
    return r;
}
__device__ __forceinline__ unsigned int smem_u32(const void* p) {
    unsigned int a;
    asm("{ .reg .u64 t; cvta.to.shared.u64 t, %1; cvt.u32.u64 %0, t; }" : "=r"(a) : "l"(p));
    return a;
}
__device__ __forceinline__ unsigned int mapa_u32(unsigned int local_addr, unsigned int peer) {
    unsigned int r;
    asm("mapa.shared::cluster.u32 %0, %1, %2;" : "=r"(r) : "r"(local_addr), "r"(peer));
    return r;
}
__device__ __forceinline__ unsigned int redux_umax(unsigned int v) {
    unsigned int r;
    asm("redux.sync.max.u32 %0, %1, 0xffffffff;" : "=r"(r) : "r"(v));
    return r;
}
__device__ __forceinline__ unsigned long long ld_acq_cluster_u64(unsigned int a) {
    unsigned long long v;
    asm volatile("ld.acquire.cluster.shared::cta.b64 %0, [%1];" : "=l"(v) : "r"(a) : "memory");
    return v;
}

// Slot: 32 bytes — [0]=seq (u64), [8]=key, [16]=xy, [24]=z_
struct __align__(16) Slot { unsigned long long seq, key, xy, z_; };

__global__ __launch_bounds__(THREADS, 1) __cluster_dims__(CL, 1, 1)
void fps_kernel(const float* __restrict__ pos, float* __restrict__ out)
{
    __shared__ unsigned long long skeys[2][16];   // [parity][warp] reduced keys
    __shared__ Slot slots[2][CL];                 // [parity][rank] exchange records

    cg::cluster_group cluster = cg::this_cluster();
    const unsigned rank = cluster.block_rank();          // 0..3
    const int b    = blockIdx.x >> 2;                    // cloud id
    const int base = (int)rank * QTR;

    const int t    = threadIdx.x;
    const int lane = t & 31;
    const int wid  = t >> 5;
    const float* p = pos + (size_t)b * PTS * 3;

    const unsigned int slots_a = smem_u32(&slots[0][0]);

    if (t == 0) {
#pragma unroll
        for (int pa = 0; pa < 2; ++pa)
#pragma unroll
            for (int r = 0; r < CL; ++r) slots[pa][r].seq = 0ull;
    }

    // This thread's 8 points: cloud-local index g = base + t + (k<<9), k=0..7.
    unsigned long long CX[PAIRS], CY[PAIRS], CZ[PAIRS];
    float d[2 * PAIRS];
    const float INF = __int_as_float(0x7f800000);

#pragma unroll
    for (int pr = 0; pr < PAIRS; ++pr) {
        int g0 = base + t + ((2 * pr)     << 9);
        int g1 = base + t + ((2 * pr + 1) << 9);
        CX[pr] = pack2(p[3 * g0 + 0], p[3 * g1 + 0]);
        CY[pr] = pack2(p[3 * g0 + 1], p[3 * g1 + 1]);
        CZ[pr] = pack2(p[3 * g0 + 2], p[3 * g1 + 2]);
        d[2 * pr]     = INF;
        d[2 * pr + 1] = INF;
    }

    float sx = p[0], sy = p[1], sz = p[2];
    if (t == 0 && rank == 0) out[b * M_SAMP] = (float)(b * PTS);

    // Slot seq init visible cluster-wide before any remote publish.
    cluster.sync();

    for (int i = 1; i < M_SAMP; ++i) {
        const unsigned long long nx2 = pack2(-sx, -sx);
        const unsigned long long ny2 = pack2(-sy, -sy);
        const unsigned long long nz2 = pack2(-sz, -sz);

        float best = 0.0f;
        int jj = 0;

#pragma unroll
        for (int pr = 0; pr < PAIRS; ++pr) {
            unsigned long long dx = add2(CX[pr], nx2);       // exact sub
            unsigned long long dy = add2(CY[pr], ny2);
            unsigned long long dz = add2(CZ[pr], nz2);
            unsigned long long s  = add2(add2(mul2(dx, dx), mul2(dy, dy)), mul2(dz, dz));
            float lo, hi;
            unpack2(s, lo, hi);
            {
                float nd = fminf(d[2 * pr], lo);
                d[2 * pr] = nd;
                bool c = nd > best; best = c ? nd : best; jj = c ? 2 * pr : jj;
            }
            {
                float nd = fminf(d[2 * pr + 1], hi);
                d[2 * pr + 1] = nd;
                bool c = nd > best; best = c ? nd : best; jj = c ? 2 * pr + 1 : jj;
            }
        }

        // Key: high = dist bits (>=0, order-preserving), low = ~cloud_local_idx.
        const unsigned int gidx = (unsigned int)(base + t) + ((unsigned int)jj << 9);
        const unsigned int mybits = __float_as_uint(best);
        const unsigned int myinv  = 0xFFFFFFFFu - gidx;
        const unsigned long long mykey = ((unsigned long long)mybits << 32) | myinv;

        // Warp argmax via 2 hardware reductions (identical key semantics).
        const unsigned int wbits = redux_umax(mybits);
        const unsigned int winv  = redux_umax(mybits == wbits ? myinv : 0u);
        const int par = i & 1;
        if (lane == 0)
            skeys[par][wid] = ((unsigned long long)wbits << 32) | winv;
        __syncthreads();                                   // (A) — only CTA barrier

        unsigned long long kbest = skeys[par][0];
#pragma unroll
        for (int w = 1; w < 16; ++w) {
            unsigned long long o = skeys[par][w];
            if (o > kbest) kbest = o;
        }

        // UNIQUE owner publishes {key, coords} + seq=i into ALL CTAs' slots.
        if (mykey == kbest) {
            const int prw = jj >> 1;
            const int hw  = jj & 1;
            float wx = 0.f, wy = 0.f, wz = 0.f;
#pragma unroll
            for (int pr = 0; pr < PAIRS; ++pr) {
                if (pr == prw) {
                    float l0, h0, l1, h1, l2, h2;
                    unpack2(CX[pr], l0, h0);
                    unpack2(CY[pr], l1, h1);
                    unpack2(CZ[pr], l2, h2);
                    wx = hw ? h0 : l0;
                    wy = hw ? h1 : l1;
                    wz = hw ? h2 : l2;
                }
            }
            const unsigned long long xy = pack2(wx, wy);
            const unsigned long long zz = pack2(wz, 0.0f);
            const unsigned int my_slot =
                slots_a + (unsigned)(par * CL + (int)rank) * sizeof(Slot);
#pragma unroll
            for (unsigned r = 0; r < CL; ++r) {
                const unsigned int rs = mapa_u32(my_slot, r);
                asm volatile("st.shared::cluster.b64 [%0+8],  %1;" :: "r"(rs), "l"(kbest) : "memory");
                asm volatile("st.shared::cluster.b64 [%0+16], %1;" :: "r"(rs), "l"(xy)    : "memory");
                asm volatile("st.shared::cluster.b64 [%0+24], %1;" :: "r"(rs), "l"(zz)    : "memory");
                asm volatile("st.release.cluster.shared::cluster.b64 [%0], %1;"
                             :: "r"(rs), "l"((unsigned long long)i) : "memory");
            }
        }

        // Spin on LOCAL smem seq words until all 4 records for iter i landed.
        {
            const unsigned int sbase = slots_a + (unsigned)(par * CL) * sizeof(Slot);
#pragma unroll
            for (int r = 0; r < CL; ++r) {
                const unsigned int sa = sbase + (unsigned)r * sizeof(Slot);
                while (ld_acq_cluster_u64(sa) != (unsigned long long)i) { }
            }
        }

        // Combine 4 records (keys globally unique).
        const Slot* sp = slots[par];
        unsigned long long gk = sp[0].key;
        int wi = 0;
#pragma unroll
        for (int w = 1; w < CL; ++w) {
            unsigned long long o = sp[w].key;
            if (o > gk) { gk = o; wi = w; }
        }
        float zlo, zhi;
        unpack2(sp[wi].xy, sx, sy);
        unpack2(sp[wi].z_, zlo, zhi);
        sz = zlo;

        if (t == 0 && rank == 0) {
            const unsigned int gw = 0xFFFFFFFFu - (unsigned int)gk;
            out[b * M_SAMP + i] = (float)(b * PTS + (int)gw);
        }
    }

    // No CTA may exit while peers might still write into its smem slots.
    cluster.sync();
}

extern "C" void kernel_launch(void* const* d_in, const int* in_sizes, int n_in,
                              void* d_out, int out_size)
{
    // Resolve pos BY SIZE (786432 floats), robust to input ordering.
    const float* pos = nullptr;
    for (int i = 0; i < n_in; ++i) {
        if (in_sizes[i] == N_CLOUDS * PTS * 3) { pos = (const float*)d_in[i]; break; }
    }
    if (!pos) pos = (const float*)d_in[0];

    float* out = (float*)d_out;   // [N_CLOUDS*M_SAMP] float32 index values

    fps_kernel<<<N_CLOUDS * CL, THREADS>>>(pos, out);
}

// round 13
// speedup vs baseline: 1.5108x; 1.5108x over previous
#include <cuda_runtime.h>
#include <cooperative_groups.h>

namespace cg = cooperative_groups;

// FPS, torch_geometric semantics. 16 clouds x 16384 -> 4096 samples/cloud.
// 4-CTA cluster per cloud (64 CTAs), 4096 points per CTA, min-dists in regs.
// Cross-CTA exchange: R11's PROVEN protocol — DSMEM slot stores + cluster.sync.
// (mbarrier handshake R9/R10 and seqnum polling R12 both measured slower.)
// Warp reduce via redux.sync.max.u32 (bit-identical key semantics, validated R12).
// Bit-exact arithmetic (validated R6+): d=(dx*dx+dy*dy)+dz*dz, RN, no FMA
// contraction, sub = add of negated. argmax = first occurrence (lowest index).
// Output: float32 values of global indices.

#define N_CLOUDS 16
#define PTS      16384
#define M_SAMP   4096
#define THREADS  512
#define CL       4
#define QTR      4096    // points per CTA
#define PAIRS    4       // 8 points per thread = 4 f32x2 pairs

__device__ __forceinline__ unsigned long long pack2(float lo, float hi) {
    unsigned long long r;
    asm("mov.b64 %0, {%1, %2};" : "=l"(r) : "f"(lo), "f"(hi));
    return r;
}
__device__ __forceinline__ void unpack2(unsigned long long v, float& lo, float& hi) {
    asm("mov.b64 {%0, %1}, %2;" : "=f"(lo), "=f"(hi) : "l"(v));
}
// Packed IEEE RN f32x2 ops (sm_100+): bit-identical to scalar FADD/FMUL.
__device__ __forceinline__ unsigned long long add2(unsigned long long a, unsigned long long b) {
    unsigned long long r;
    asm("add.rn.f32x2 %0, %1, %2;" : "=l"(r) : "l"(a), "l"(b));
    return r;
}
__device__ __forceinline__ unsigned long long mul2(unsigned long long a, unsigned long long b) {
    unsigned long long r;
    asm("mul.rn.f32x2 %0, %1, %2;" : "=l"(r) : "l"(a), "l"(b));
    return r;
}
__device__ __forceinline__ unsigned int redux_umax(unsigned int v) {
    unsigned int r;
    asm("redux.sync.max.u32 %0, %1, 0xffffffff;" : "=r"(r) : "r"(v));
    return r;
}

struct __align__(8) Slot { unsigned long long key; float x, y, z; };

__global__ __launch_bounds__(THREADS, 1) __cluster_dims__(CL, 1, 1)
void fps_kernel(const float* __restrict__ pos, float* __restrict__ out)
{
    __shared__ unsigned long long skeys[2][16];   // [parity][warp] reduced keys
    __shared__ Slot slots[2][CL];                 // [parity][rank] exchange records

    cg::cluster_group cluster = cg::this_cluster();
    const unsigned rank = cluster.block_rank();          // 0..3
    const int b    = blockIdx.x >> 2;                    // cloud id
    const int base = (int)rank * QTR;                    // cloud-local CTA offset

    const int t    = threadIdx.x;
    const int lane = t & 31;
    const int wid  = t >> 5;
    const float* p = pos + (size_t)b * PTS * 3;

    // This thread's 8 points: cloud-local index g = base + t + (k<<9), k=0..7.
    unsigned long long CX[PAIRS], CY[PAIRS], CZ[PAIRS];
    float d[2 * PAIRS];
    const float INF = __int_as_float(0x7f800000);

#pragma unroll
    for (int pr = 0; pr < PAIRS; ++pr) {
        int g0 = base + t + ((2 * pr)     << 9);
        int g1 = base + t + ((2 * pr + 1) << 9);
        CX[pr] = pack2(p[3 * g0 + 0], p[3 * g1 + 0]);
        CY[pr] = pack2(p[3 * g0 + 1], p[3 * g1 + 1]);
        CZ[pr] = pack2(p[3 * g0 + 2], p[3 * g1 + 2]);
        d[2 * pr]     = INF;
        d[2 * pr + 1] = INF;
    }

    // First pick: cloud-local index 0 (L1-broadcast load by all threads).
    float sx = p[0], sy = p[1], sz = p[2];
    if (t == 0 && rank == 0) out[b * M_SAMP] = (float)(b * PTS);

    // Whole cluster alive before the per-iteration protocol.
    cluster.sync();

    for (int i = 1; i < M_SAMP; ++i) {
        const unsigned long long nx2 = pack2(-sx, -sx);
        const unsigned long long ny2 = pack2(-sy, -sy);
        const unsigned long long nz2 = pack2(-sz, -sz);

        float best = 0.0f;
        int jj = 0;

#pragma unroll
        for (int pr = 0; pr < PAIRS; ++pr) {
            unsigned long long dx = add2(CX[pr], nx2);       // exact sub
            unsigned long long dy = add2(CY[pr], ny2);
            unsigned long long dz = add2(CZ[pr], nz2);
            unsigned long long s  = add2(add2(mul2(dx, dx), mul2(dy, dy)), mul2(dz, dz));
            float lo, hi;
            unpack2(s, lo, hi);
            {
                float nd = fminf(d[2 * pr], lo);
                d[2 * pr] = nd;
                bool c = nd > best; best = c ? nd : best; jj = c ? 2 * pr : jj;
            }
            {
                float nd = fminf(d[2 * pr + 1], hi);
                d[2 * pr + 1] = nd;
                bool c = nd > best; best = c ? nd : best; jj = c ? 2 * pr + 1 : jj;
            }
        }

        // Key: high = dist bits (>=0, order-preserving), low = ~cloud_local_idx
        // (ties break toward the LOWEST index == jnp.argmax first-occurrence).
        const unsigned int gidx = (unsigned int)(base + t) + ((unsigned int)jj << 9);
        const unsigned int mybits = __float_as_uint(best);
        const unsigned int myinv  = 0xFFFFFFFFu - gidx;
        const unsigned long long mykey = ((unsigned long long)mybits << 32) | myinv;

        // Warp argmax via 2 hardware reductions (bit-identical to u64 shuffle max).
        const unsigned int wbits = redux_umax(mybits);
        const unsigned int winv  = redux_umax(mybits == wbits ? myinv : 0u);

        const int par = i & 1;
        if (lane == 0)
            skeys[par][wid] = ((unsigned long long)wbits << 32) | winv;
        __syncthreads();                                   // (A)

        unsigned long long kbest = skeys[par][0];
#pragma unroll
        for (int w = 1; w < 16; ++w) {
            unsigned long long o = skeys[par][w];
            if (o > kbest) kbest = o;
        }

        // UNIQUE owner (pre-reduction key == CTA max) publishes {key, coords}
        // to its slot in ALL CTAs (local + 3 peers via DSMEM).
        if (mykey == kbest) {
            const int prw = jj >> 1;
            const int hw  = jj & 1;
            float wx = 0.f, wy = 0.f, wz = 0.f;
#pragma unroll
            for (int pr = 0; pr < PAIRS; ++pr) {
                if (pr == prw) {
                    float l0, h0, l1, h1, l2, h2;
                    unpack2(CX[pr], l0, h0);
                    unpack2(CY[pr], l1, h1);
                    unpack2(CZ[pr], l2, h2);
                    wx = hw ? h0 : l0;
                    wy = hw ? h1 : l1;
                    wz = hw ? h2 : l2;
                }
            }
            // Local record
            slots[par][rank].key = kbest;
            slots[par][rank].x = wx;
            slots[par][rank].y = wy;
            slots[par][rank].z = wz;
            // Peer records via DSMEM (ordering provided by cluster.sync below)
#pragma unroll
            for (unsigned pr_ = 1; pr_ < CL; ++pr_) {
                const unsigned peer = (rank + pr_) & (CL - 1);
                Slot* rs = cluster.map_shared_rank(&slots[par][rank], peer);
                rs->key = kbest;
                rs->x = wx; rs->y = wy; rs->z = wz;
            }
        }

        // Orders publishes before reads; second CTA barrier of the iteration
        // (skeys and slots are parity-double-buffered).
        cluster.sync();

        const Slot* sp = slots[par];
        unsigned long long gk = sp[0].key;
        int wi = 0;
#pragma unroll
        for (int w = 1; w < CL; ++w) {
            unsigned long long o = sp[w].key;
            if (o > gk) { gk = o; wi = w; }
        }
        sx = sp[wi].x; sy = sp[wi].y; sz = sp[wi].z;

        if (t == 0 && rank == 0) {
            const unsigned int gw = 0xFFFFFFFFu - (unsigned int)gk;
            out[b * M_SAMP + i] = (float)(b * PTS + (int)gw);
        }
    }
}

extern "C" void kernel_launch(void* const* d_in, const int* in_sizes, int n_in,
                              void* d_out, int out_size)
{
    // Resolve pos BY SIZE (786432 floats), robust to input ordering.
    const float* pos = nullptr;
    for (int i = 0; i < n_in; ++i) {
        if (in_sizes[i] == N_CLOUDS * PTS * 3) { pos = (const float*)d_in[i]; break; }
    }
    if (!pos) pos = (const float*)d_in[0];

    float* out = (float*)d_out;   // [N_CLOUDS*M_SAMP] float32 index values

    fps_kernel<<<N_CLOUDS * CL, THREADS>>>(pos, out);
}